// round 8
// baseline (speedup 1.0000x reference)
#include <cuda_runtime.h>
#include <cuda_bf16.h>
#include <cstdint>

#define BB 4
#define SS 2048
#define DD 512
#define HH 8
#define HD 64

__device__ __nv_bfloat16 g_xh[(size_t)BB * SS * DD];
__device__ __nv_bfloat16 g_xl[(size_t)BB * SS * DD];
__device__ __nv_bfloat16 g_wh[(size_t)DD * DD];
__device__ __nv_bfloat16 g_wl[(size_t)DD * DD];
__device__ __nv_bfloat16 g_kh[(size_t)BB * HH * SS * HD];
__device__ __nv_bfloat16 g_kl[(size_t)BB * HH * SS * HD];

__device__ __forceinline__ uint32_t pack2(__nv_bfloat16 lo, __nv_bfloat16 hi) {
    return ((uint32_t)__bfloat16_as_ushort(hi) << 16) |
           (uint32_t)__bfloat16_as_ushort(lo);
}

// ===========================================================================
// Conversion pre-kernels (unchanged)
// ===========================================================================
__global__ void conv_x(const float* __restrict__ x) {
    size_t i = ((size_t)blockIdx.x * 256 + threadIdx.x) * 4;
    float4 v = *(const float4*)(x + i);
    __nv_bfloat16 h0 = __float2bfloat16(v.x), h1 = __float2bfloat16(v.y);
    __nv_bfloat16 h2 = __float2bfloat16(v.z), h3 = __float2bfloat16(v.w);
    __nv_bfloat16 l0 = __float2bfloat16(v.x - __bfloat162float(h0));
    __nv_bfloat16 l1 = __float2bfloat16(v.y - __bfloat162float(h1));
    __nv_bfloat16 l2 = __float2bfloat16(v.z - __bfloat162float(h2));
    __nv_bfloat16 l3 = __float2bfloat16(v.w - __bfloat162float(h3));
    *(uint2*)&g_xh[i] = make_uint2(pack2(h0, h1), pack2(h2, h3));
    *(uint2*)&g_xl[i] = make_uint2(pack2(l0, l1), pack2(l2, l3));
}

__global__ void conv_w(const float* __restrict__ Wq) {
    __shared__ float t[32][33];
    const int bx = blockIdx.x * 32, by = blockIdx.y * 32;
    const int tx = threadIdx.x, ty = threadIdx.y;
    #pragma unroll
    for (int j = 0; j < 4; j++)
        t[ty + 8 * j][tx] = Wq[(size_t)(by + ty + 8 * j) * DD + bx + tx];
    __syncthreads();
    #pragma unroll
    for (int j = 0; j < 4; j++) {
        float v = t[tx][ty + 8 * j];
        __nv_bfloat16 h = __float2bfloat16(v);
        __nv_bfloat16 l = __float2bfloat16(v - __bfloat162float(h));
        size_t o = (size_t)(bx + ty + 8 * j) * DD + by + tx;
        g_wh[o] = h;
        g_wl[o] = l;
    }
}

// ===========================================================================
// HMMA / cp.async helpers
// ===========================================================================
__device__ __forceinline__ uint32_t smem_u32(const void* p) {
    uint32_t a;
    asm("{ .reg .u64 t; cvta.to.shared.u64 t, %1; cvt.u32.u64 %0, t; }"
        : "=r"(a) : "l"(p));
    return a;
}

#define LDSM_X4(r0, r1, r2, r3, addr)                                         \
    asm volatile("ldmatrix.sync.aligned.m8n8.x4.shared.b16 {%0,%1,%2,%3}, [%4];" \
                 : "=r"(r0), "=r"(r1), "=r"(r2), "=r"(r3) : "r"(addr))

#define LDSM_T_X4(r0, r1, r2, r3, addr)                                       \
    asm volatile("ldmatrix.sync.aligned.m8n8.x4.trans.shared.b16 {%0,%1,%2,%3}, [%4];" \
                 : "=r"(r0), "=r"(r1), "=r"(r2), "=r"(r3) : "r"(addr))

__device__ __forceinline__ void mma16816(float* d, const uint32_t* a,
                                         uint32_t b0, uint32_t b1) {
    asm volatile(
        "mma.sync.aligned.m16n8k16.row.col.f32.bf16.bf16.f32 "
        "{%0,%1,%2,%3}, {%4,%5,%6,%7}, {%8,%9}, {%0,%1,%2,%3};"
        : "+f"(d[0]), "+f"(d[1]), "+f"(d[2]), "+f"(d[3])
        : "r"(a[0]), "r"(a[1]), "r"(a[2]), "r"(a[3]), "r"(b0), "r"(b1));
}

#define CPA(dst, src) \
    asm volatile("cp.async.cg.shared.global [%0], [%1], 16;" :: "r"(dst), "l"(src))
#define CPC() asm volatile("cp.async.commit_group;" ::: "memory")
#define CPW(n) asm volatile("cp.async.wait_group %0;" :: "n"(n) : "memory")

// ===========================================================================
// Projection GEMM on HMMA (unchanged from round 7)
// ===========================================================================
static constexpr uint32_t JPITCH  = 144;
static constexpr uint32_t JXPLANE = 128 * JPITCH;
static constexpr uint32_t JP_WH   = 2 * JXPLANE;
static constexpr uint32_t JWPLANE = 64 * JPITCH;
static constexpr uint32_t JSTAGE  = JP_WH + 2 * JWPLANE;
static constexpr uint32_t PROJ_SMEM = 2 * JSTAGE;

__device__ __forceinline__ void proj_prefetch(uint32_t st, int m0, int n0, int kc,
                                              int tid) {
    const __nv_bfloat16* xh = g_xh + (size_t)m0 * DD + kc * 64;
    const __nv_bfloat16* xl = g_xl + (size_t)m0 * DD + kc * 64;
    #pragma unroll
    for (int it = 0; it < 4; it++) {
        int idx = tid + it * 256;
        int row = idx >> 3, c = idx & 7;
        uint32_t d = (uint32_t)row * JPITCH + c * 16;
        CPA(st + d, (const char*)(xh + (size_t)row * DD + c * 8));
        CPA(st + JXPLANE + d, (const char*)(xl + (size_t)row * DD + c * 8));
    }
    const __nv_bfloat16* wh = g_wh + (size_t)n0 * DD + kc * 64;
    const __nv_bfloat16* wl = g_wl + (size_t)n0 * DD + kc * 64;
    #pragma unroll
    for (int it = 0; it < 2; it++) {
        int idx = tid + it * 256;
        int row = idx >> 3, c = idx & 7;
        uint32_t d = (uint32_t)row * JPITCH + c * 16;
        CPA(st + JP_WH + d, (const char*)(wh + (size_t)row * DD + c * 8));
        CPA(st + JP_WH + JWPLANE + d, (const char*)(wl + (size_t)row * DD + c * 8));
    }
}

__global__ void __launch_bounds__(256, 2) proj_hmma(int dummy) {
    extern __shared__ char smem[];
    const uint32_t sb = smem_u32(smem);
    const int tid = threadIdx.x;
    const int lane = tid & 31, w = tid >> 5;
    const int m0 = blockIdx.x * 128;
    const int h  = blockIdx.y;
    const int n0 = h * 64;

    proj_prefetch(sb, m0, n0, 0, tid);
    CPC();

    float acc[8][4] = {};
    const uint32_t arow = (uint32_t)(w * 16 + (lane & 15)) * JPITCH
                        + (uint32_t)(lane >> 4) * 16;
    const uint32_t wrow = JP_WH + (uint32_t)(lane & 7) * JPITCH
                        + (uint32_t)(lane >> 3) * 16;

    for (int kc = 0; kc < 8; kc++) {
        const uint32_t st = sb + (uint32_t)(kc & 1) * JSTAGE;
        if (kc + 1 < 8) {
            proj_prefetch(sb + (uint32_t)((kc + 1) & 1) * JSTAGE, m0, n0, kc + 1, tid);
            CPC();
            CPW(1);
        } else {
            CPW(0);
        }
        __syncthreads();

        uint32_t ah[4][4], al[4][4];
        #pragma unroll
        for (int i = 0; i < 4; i++) {
            LDSM_X4(ah[i][0], ah[i][1], ah[i][2], ah[i][3], st + arow + i * 32);
            LDSM_X4(al[i][0], al[i][1], al[i][2], al[i][3],
                    st + arow + JXPLANE + i * 32);
        }
        #pragma unroll
        for (int jj = 0; jj < 8; jj++) {
            uint32_t a = st + wrow + (uint32_t)jj * 8 * JPITCH;
            uint32_t bh_[8], bl_[8];
            LDSM_X4(bh_[0], bh_[1], bh_[2], bh_[3], a);
            LDSM_X4(bh_[4], bh_[5], bh_[6], bh_[7], a + 64);
            LDSM_X4(bl_[0], bl_[1], bl_[2], bl_[3], a + JWPLANE);
            LDSM_X4(bl_[4], bl_[5], bl_[6], bl_[7], a + JWPLANE + 64);
            #pragma unroll
            for (int i = 0; i < 4; i++) {
                mma16816(acc[jj], ah[i], bh_[2 * i], bh_[2 * i + 1]);
                mma16816(acc[jj], ah[i], bl_[2 * i], bl_[2 * i + 1]);
                mma16816(acc[jj], al[i], bh_[2 * i], bh_[2 * i + 1]);
            }
        }
        __syncthreads();
    }

    const int r0g = m0 + w * 16 + (lane >> 2);
    const int b   = r0g >> 11;
    const int s0  = r0g & (SS - 1);
    const int bh_i = b * HH + h;
    const int c2  = (lane & 3) * 2;

    #pragma unroll
    for (int jj = 0; jj < 8; jj++) {
        int c = jj * 8 + c2;
        __nv_bfloat16 h0 = __float2bfloat16(acc[jj][0]);
        __nv_bfloat16 h1 = __float2bfloat16(acc[jj][1]);
        __nv_bfloat16 h2 = __float2bfloat16(acc[jj][2]);
        __nv_bfloat16 h3 = __float2bfloat16(acc[jj][3]);
        __nv_bfloat16 l0 = __float2bfloat16(acc[jj][0] - __bfloat162float(h0));
        __nv_bfloat16 l1 = __float2bfloat16(acc[jj][1] - __bfloat162float(h1));
        __nv_bfloat16 l2 = __float2bfloat16(acc[jj][2] - __bfloat162float(h2));
        __nv_bfloat16 l3 = __float2bfloat16(acc[jj][3] - __bfloat162float(h3));

        size_t ka = ((size_t)bh_i * SS + s0) * HD + c;
        *(uint32_t*)&g_kh[ka] = pack2(h0, h1);
        *(uint32_t*)&g_kl[ka] = pack2(l0, l1);
        *(uint32_t*)&g_kh[ka + 8 * HD] = pack2(h2, h3);
        *(uint32_t*)&g_kl[ka + 8 * HD] = pack2(l2, l3);
    }
}

// ===========================================================================
// Attention: 32 Q-rows per warp (2 M-blocks), K/V frags amortized 2x.
// CTA = 256 Q rows, 8 warps, occ 1. grid (SS/256, H, B).
// ===========================================================================
static constexpr uint32_t KPITCH  = 144;
static constexpr uint32_t KPLANE  = 128 * KPITCH;          // 18432
static constexpr uint32_t KSTAGE  = 2 * KPLANE;            // 36864
static constexpr uint32_t SMEM_BYTES = 2 * KSTAGE;         // 73728

__device__ __forceinline__ void prefetch_k(uint32_t stage_base,
                                           const __nv_bfloat16* kh,
                                           const __nv_bfloat16* kl, int tid) {
    #pragma unroll
    for (int it = 0; it < 4; it++) {
        int idx = tid + it * 256;
        int row = idx >> 3, c = idx & 7;
        uint32_t d = (uint32_t)row * KPITCH + c * 16;
        CPA(stage_base + d, (const char*)(kh + (size_t)row * HD + c * 8));
        CPA(stage_base + KPLANE + d, (const char*)(kl + (size_t)row * HD + c * 8));
    }
}

__device__ __forceinline__ void load_qfrag(uint32_t qf[4][4], const uint32_t* qp,
                                           int row0, int lane) {
    const int r = lane >> 2, c2 = (lane & 3) * 2;
    #pragma unroll
    for (int kc = 0; kc < 4; kc++) {
        int base = (row0 + r) * HD + kc * 16 + c2;
        qf[kc][0] = qp[(base              ) >> 1];
        qf[kc][1] = qp[(base + 8 * HD     ) >> 1];
        qf[kc][2] = qp[(base + 8          ) >> 1];
        qf[kc][3] = qp[(base + 8 * HD + 8 ) >> 1];
    }
}

__global__ void __launch_bounds__(256, 1) attn_kernel(float* __restrict__ out) {
    extern __shared__ char smem[];
    const uint32_t sb = smem_u32(smem);
    const int tid = threadIdx.x;
    const int lane = tid & 31, w = tid >> 5;
    const int qb = blockIdx.x, h = blockIdx.y, b = blockIdx.z;
    const int bh = b * HH + h;
    const int NT = SS / 128;

    const __nv_bfloat16* khb = g_kh + (size_t)bh * SS * HD;
    const __nv_bfloat16* klb = g_kl + (size_t)bh * SS * HD;

    prefetch_k(sb, khb, klb, tid);
    CPC();

    // Q fragments for two 16-row M-blocks: rows qb*256 + w*16 (+128)
    uint32_t qh0[4][4], ql0[4][4], qh1[4][4], ql1[4][4];
    {
        const uint32_t* qhp = (const uint32_t*)(khb + (size_t)(qb * 256) * HD);
        const uint32_t* qlp = (const uint32_t*)(klb + (size_t)(qb * 256) * HD);
        load_qfrag(qh0, qhp, w * 16, lane);
        load_qfrag(ql0, qlp, w * 16, lane);
        load_qfrag(qh1, qhp, 128 + w * 16, lane);
        load_qfrag(ql1, qlp, 128 + w * 16, lane);
    }

    float O0[8][4] = {}, O1[8][4] = {};
    float l00 = 0.f, l01 = 0.f, l10 = 0.f, l11 = 0.f;

    const uint32_t krow = (uint32_t)(lane & 7) * KPITCH + (uint32_t)(lane >> 3) * 16;

    for (int kb = 0; kb < NT; kb++) {
        const uint32_t st = sb + (uint32_t)(kb & 1) * KSTAGE;

        __syncthreads();
        if (kb + 1 < NT) {
            prefetch_k(sb + (uint32_t)((kb + 1) & 1) * KSTAGE,
                       khb + (size_t)(kb + 1) * 128 * HD,
                       klb + (size_t)(kb + 1) * 128 * HD, tid);
            CPC();
            CPW(1);
        } else {
            CPW(0);
        }
        __syncthreads();

        // process the 128-kv tile in four 32-kv chunks: S -> softmax -> PV
        #pragma unroll
        for (int c32 = 0; c32 < 4; c32++) {
            uint32_t ph0[2][4], ph1[2][4];
            // ---- S for this 32-kv chunk (both M-blocks share B-frags) ----
            #pragma unroll
            for (int j2 = 0; j2 < 4; j2++) {
                int jj = c32 * 4 + j2;
                uint32_t a = st + krow + (uint32_t)jj * 8 * KPITCH;
                uint32_t kh_[8], kl_[8];
                LDSM_X4(kh_[0], kh_[1], kh_[2], kh_[3], a);
                LDSM_X4(kh_[4], kh_[5], kh_[6], kh_[7], a + 64);
                LDSM_X4(kl_[0], kl_[1], kl_[2], kl_[3], a + KPLANE);
                LDSM_X4(kl_[4], kl_[5], kl_[6], kl_[7], a + KPLANE + 64);
                float Sa[4] = {}, Sb[4] = {};
                #pragma unroll
                for (int kc = 0; kc < 4; kc++) {
                    mma16816(Sa, qh0[kc], kh_[2 * kc], kh_[2 * kc + 1]);
                    mma16816(Sb, qh1[kc], kh_[2 * kc], kh_[2 * kc + 1]);
                    mma16816(Sa, qh0[kc], kl_[2 * kc], kl_[2 * kc + 1]);
                    mma16816(Sb, qh1[kc], kl_[2 * kc], kl_[2 * kc + 1]);
                    mma16816(Sa, ql0[kc], kh_[2 * kc], kh_[2 * kc + 1]);
                    mma16816(Sb, ql1[kc], kh_[2 * kc], kh_[2 * kc + 1]);
                }
                // softmax both blocks
                __nv_bfloat16 p0 = __float2bfloat16(__expf(Sa[0] * 0.125f));
                __nv_bfloat16 p1 = __float2bfloat16(__expf(Sa[1] * 0.125f));
                __nv_bfloat16 p2 = __float2bfloat16(__expf(Sa[2] * 0.125f));
                __nv_bfloat16 p3 = __float2bfloat16(__expf(Sa[3] * 0.125f));
                l00 += __bfloat162float(p0) + __bfloat162float(p1);
                l01 += __bfloat162float(p2) + __bfloat162float(p3);
                __nv_bfloat16 r0 = __float2bfloat16(__expf(Sb[0] * 0.125f));
                __nv_bfloat16 r1 = __float2bfloat16(__expf(Sb[1] * 0.125f));
                __nv_bfloat16 r2 = __float2bfloat16(__expf(Sb[2] * 0.125f));
                __nv_bfloat16 r3 = __float2bfloat16(__expf(Sb[3] * 0.125f));
                l10 += __bfloat162float(r0) + __bfloat162float(r1);
                l11 += __bfloat162float(r2) + __bfloat162float(r3);
                int kc16 = j2 >> 1, o = (j2 & 1) * 2;
                ph0[kc16][o]     = pack2(p0, p1);
                ph0[kc16][o + 1] = pack2(p2, p3);
                ph1[kc16][o]     = pack2(r0, r1);
                ph1[kc16][o + 1] = pack2(r2, r3);
            }

            // ---- PV for this chunk (trans B-frags shared by both M-blocks) ----
            uint32_t rowa = st + (uint32_t)(c32 * 32 + lane) * KPITCH;
            #pragma unroll
            for (int dj = 0; dj < 8; dj++) {
                uint32_t a = rowa + (uint32_t)dj * 16;
                uint32_t th[4], tl[4];
                LDSM_T_X4(th[0], th[1], th[2], th[3], a);
                LDSM_T_X4(tl[0], tl[1], tl[2], tl[3], a + KPLANE);
                mma16816(O0[dj], ph0[0], th[0], th[1]);
                mma16816(O1[dj], ph1[0], th[0], th[1]);
                mma16816(O0[dj], ph0[0], tl[0], tl[1]);
                mma16816(O1[dj], ph1[0], tl[0], tl[1]);
                mma16816(O0[dj], ph0[1], th[2], th[3]);
                mma16816(O1[dj], ph1[1], th[2], th[3]);
                mma16816(O0[dj], ph0[1], tl[2], tl[3]);
                mma16816(O1[dj], ph1[1], tl[2], tl[3]);
            }
        }
    }

    // ---- epilogue (both M-blocks) ----
    l00 += __shfl_xor_sync(0xffffffffu, l00, 1);
    l00 += __shfl_xor_sync(0xffffffffu, l00, 2);
    l01 += __shfl_xor_sync(0xffffffffu, l01, 1);
    l01 += __shfl_xor_sync(0xffffffffu, l01, 2);
    l10 += __shfl_xor_sync(0xffffffffu, l10, 1);
    l10 += __shfl_xor_sync(0xffffffffu, l10, 2);
    l11 += __shfl_xor_sync(0xffffffffu, l11, 1);
    l11 += __shfl_xor_sync(0xffffffffu, l11, 2);
    float i00 = 1.f / l00, i01 = 1.f / l01;
    float i10 = 1.f / l10, i11 = 1.f / l11;

    {
        int r0 = qb * 256 + w * 16 + (lane >> 2);
        float* o0 = out + ((size_t)(b * SS + r0)) * DD + h * HD + (lane & 3) * 2;
        float* o1 = o0 + 8 * DD;
        float* o2 = o0 + (size_t)128 * DD;
        float* o3 = o2 + 8 * DD;
        #pragma unroll
        for (int jj = 0; jj < 8; jj++) {
            *(float2*)(o0 + jj * 8) = make_float2(O0[jj][0] * i00, O0[jj][1] * i00);
            *(float2*)(o1 + jj * 8) = make_float2(O0[jj][2] * i01, O0[jj][3] * i01);
            *(float2*)(o2 + jj * 8) = make_float2(O1[jj][0] * i10, O1[jj][1] * i10);
            *(float2*)(o3 + jj * 8) = make_float2(O1[jj][2] * i11, O1[jj][3] * i11);
        }
    }
}

extern "C" void kernel_launch(void* const* d_in, const int* in_sizes, int n_in,
                              void* d_out, int out_size) {
    const float* x  = (const float*)d_in[0];
    const float* Wq = (const float*)d_in[1];
    float* out = (float*)d_out;

    cudaFuncSetAttribute(proj_hmma, cudaFuncAttributeMaxDynamicSharedMemorySize,
                         PROJ_SMEM);
    cudaFuncSetAttribute(attn_kernel, cudaFuncAttributeMaxDynamicSharedMemorySize,
                         SMEM_BYTES);

    conv_x<<<(BB * SS * DD) / (256 * 4), 256>>>(x);
    conv_w<<<dim3(DD / 32, DD / 32), dim3(32, 8)>>>(Wq);
    proj_hmma<<<dim3((BB * SS) / 128, HH), 256, PROJ_SMEM>>>(0);
    attn_kernel<<<dim3(SS / 256, HH, BB), 256, SMEM_BYTES>>>(out);
}